// round 1
// baseline (speedup 1.0000x reference)
#include <cuda_runtime.h>
#include <math.h>

// Problem constants
#define BB   2
#define SS   2048
#define HID  4096
#define NH   32
#define NKV  8
#define DD   128
#define TT   (BB*SS)       // 4096 tokens
#define GROUPS (NH/NKV)    // 4

// ---------------- scratch (device globals; no allocation allowed) ----------------
__device__ float g_q   [(size_t)TT * (NH*DD)];     // QKV proj outputs, token-major
__device__ float g_k   [(size_t)TT * (NKV*DD)];
__device__ float g_v   [(size_t)TT * (NKV*DD)];
__device__ float g_Qh  [(size_t)BB * NH  * SS * DD];   // [b,h,s,d], pre-scaled by 1/sqrt(D)
__device__ float g_KhT [(size_t)BB * NKV * DD * SS];   // [b,kh,d,s] (transposed for flash)
__device__ float g_Vh  [(size_t)BB * NKV * SS * DD];   // [b,kh,s,d]
__device__ float g_attn[(size_t)TT * (NH*DD)];         // attention out, token-major

// ---------------- SGEMM: C[M,N] = A[M,K] @ B[K,N], all row-major, fp32 ----------------
// BM=128, BN=128, BK=16, 256 threads, 8x8 per thread. Dims are multiples of tiles.
__global__ __launch_bounds__(256) void sgemm_kernel(
    const float* __restrict__ A, const float* __restrict__ Bw, float* __restrict__ C,
    int M, int N, int K)
{
    __shared__ float As[16][132];   // padded, stored transposed: As[k][m]
    __shared__ float Bs[16][128];

    int tid = threadIdx.x;
    int tx = tid & 15;          // 0..15 -> N
    int ty = tid >> 4;          // 0..15 -> M

    const float* Ab = A + (size_t)blockIdx.y * 128 * K;
    const float* Bb = Bw + (size_t)blockIdx.x * 128;

    float acc[8][8];
#pragma unroll
    for (int i = 0; i < 8; i++)
#pragma unroll
        for (int j = 0; j < 8; j++) acc[i][j] = 0.f;

    for (int kb = 0; kb < K; kb += 16) {
        // load A tile (128x16) -> As transposed
#pragma unroll
        for (int l = 0; l < 2; l++) {
            int idx  = tid + l * 256;       // 0..511 float4s
            int arow = idx >> 2;            // 0..127
            int ac4  = idx & 3;             // 0..3
            float4 a = *(const float4*)(Ab + (size_t)arow * K + kb + ac4 * 4);
            As[ac4*4+0][arow] = a.x;
            As[ac4*4+1][arow] = a.y;
            As[ac4*4+2][arow] = a.z;
            As[ac4*4+3][arow] = a.w;
        }
        // load B tile (16x128)
#pragma unroll
        for (int l = 0; l < 2; l++) {
            int idx  = tid + l * 256;
            int brow = idx >> 5;            // 0..15
            int bc4  = idx & 31;            // 0..31
            *(float4*)&Bs[brow][bc4*4] =
                *(const float4*)(Bb + (size_t)(kb + brow) * N + bc4 * 4);
        }
        __syncthreads();

#pragma unroll
        for (int k = 0; k < 16; k++) {
            float ar[8], br[8];
            *(float4*)(ar)     = *(const float4*)&As[k][ty*8];
            *(float4*)(ar + 4) = *(const float4*)&As[k][ty*8 + 4];
            *(float4*)(br)     = *(const float4*)&Bs[k][tx*8];
            *(float4*)(br + 4) = *(const float4*)&Bs[k][tx*8 + 4];
#pragma unroll
            for (int i = 0; i < 8; i++)
#pragma unroll
                for (int j = 0; j < 8; j++)
                    acc[i][j] += ar[i] * br[j];
        }
        __syncthreads();
    }

#pragma unroll
    for (int i = 0; i < 8; i++) {
        size_t row = (size_t)blockIdx.y * 128 + ty * 8 + i;
        float* Cp = C + row * N + (size_t)blockIdx.x * 128 + tx * 8;
        float4 v0 = make_float4(acc[i][0], acc[i][1], acc[i][2], acc[i][3]);
        float4 v1 = make_float4(acc[i][4], acc[i][5], acc[i][6], acc[i][7]);
        *(float4*)(Cp)     = v0;
        *(float4*)(Cp + 4) = v1;
    }
}

// ---------------- RoPE + permute kernels ----------------
// rotate_half: rot[d] = -x[d+64] (d<64) ; x[d-64] (d>=64)  -> partner = d^64
__global__ void rope_q_kernel(const float* __restrict__ cq,
                              const float* __restrict__ cosc,
                              const float* __restrict__ sinc,
                              float* __restrict__ Qh)
{
    int idx = blockIdx.x * blockDim.x + threadIdx.x;   // over TT*NH*DD = 16.7M
    int d = idx & 127;
    int h = (idx >> 7) & 31;
    int t = idx >> 12;
    int s = t & (SS - 1);
    int b = t >> 11;
    float v  = cq[idx];
    float vp = cq[idx ^ 64];
    float rot = (d < 64) ? -vp : vp;
    float c  = cosc[s * DD + d];
    float sn = sinc[s * DD + d];
    const float scale = 0.08838834764831845f;  // 1/sqrt(128), pre-scale Q
    Qh[(((size_t)(b * NH + h)) * SS + s) * DD + d] = (v * c + rot * sn) * scale;
}

__global__ void rope_k_kernel(const float* __restrict__ ck,
                              const float* __restrict__ cosc,
                              const float* __restrict__ sinc,
                              float* __restrict__ KhT)
{
    int idx = blockIdx.x * blockDim.x + threadIdx.x;   // over TT*NKV*DD = 4.2M
    int d  = idx & 127;
    int kh = (idx >> 7) & 7;
    int t  = idx >> 10;
    int s = t & (SS - 1);
    int b = t >> 11;
    float v  = ck[idx];
    float vp = ck[idx ^ 64];
    float rot = (d < 64) ? -vp : vp;
    float c  = cosc[s * DD + d];
    float sn = sinc[s * DD + d];
    // [b,kh,d,s] layout for coalesced transposed loads in flash
    KhT[(((size_t)(b * NKV + kh)) * DD + d) * SS + s] = v * c + rot * sn;
}

__global__ void perm_v_kernel(const float* __restrict__ cv, float* __restrict__ Vh)
{
    int idx = blockIdx.x * blockDim.x + threadIdx.x;   // over TT*NKV*DD
    int d  = idx & 127;
    int kh = (idx >> 7) & 7;
    int t  = idx >> 10;
    int s = t & (SS - 1);
    int b = t >> 11;
    Vh[(((size_t)(b * NKV + kh)) * SS + s) * DD + d] = cv[idx];
}

// ---------------- Flash attention (fp32, causal, GQA) ----------------
// 1 block = 64 query rows of one (b,h). 256 threads: row r = tid>>2, sub = tid&3.
// Each thread owns 16 score columns and 32 output columns of its row.
// smem: Qs[64][132], Kst[128][68] (K transposed), Vs[64][132], Ps[64][68]
#define QS_STRIDE 132
#define KS_STRIDE 68
#define PS_STRIDE 68
#define SMEM_FLOATS (64*QS_STRIDE + 128*KS_STRIDE + 64*QS_STRIDE + 64*PS_STRIDE)

__global__ __launch_bounds__(256) void flash_kernel(
    const float* __restrict__ Qh, const float* __restrict__ KhT,
    const float* __restrict__ Vh, float* __restrict__ attn)
{
    extern __shared__ float sm[];
    float* Qs  = sm;
    float* Kst = Qs + 64 * QS_STRIDE;
    float* Vs  = Kst + 128 * KS_STRIDE;
    float* Ps  = Vs + 64 * QS_STRIDE;

    int qt = blockIdx.x;         // 0..31
    int h  = blockIdx.y;         // 0..31
    int b  = blockIdx.z;         // 0..1
    int kh = h >> 2;             // GQA group
    int tid = threadIdx.x;
    int r   = tid >> 2;
    int sub = tid & 3;

    // load Q tile (already scaled by 1/sqrt(D))
    {
        int j = tid >> 2, seg = tid & 3;
        const float* src = Qh + (((size_t)(b * NH + h)) * SS + qt * 64 + j) * DD + seg * 32;
#pragma unroll
        for (int i = 0; i < 8; i++)
            *(float4*)&Qs[j * QS_STRIDE + seg * 32 + 4 * i] = *(const float4*)(src + 4 * i);
    }

    float m = -1e30f, l = 0.f;
    float o[32];
#pragma unroll
    for (int i = 0; i < 32; i++) o[i] = 0.f;

    for (int kt = 0; kt <= qt; kt++) {
        __syncthreads();   // previous iteration's smem readers done
        // load K tile transposed: Kst[d][j] from KhT[b,kh,d, kt*64+j]
        {
            int d = tid >> 1, jseg = tid & 1;
            const float* src = KhT + (((size_t)(b * NKV + kh)) * DD + d) * SS + kt * 64 + jseg * 32;
#pragma unroll
            for (int i = 0; i < 8; i++)
                *(float4*)&Kst[d * KS_STRIDE + jseg * 32 + 4 * i] = *(const float4*)(src + 4 * i);
        }
        // load V tile
        {
            int j = tid >> 2, seg = tid & 3;
            const float* src = Vh + (((size_t)(b * NKV + kh)) * SS + kt * 64 + j) * DD + seg * 32;
#pragma unroll
            for (int i = 0; i < 8; i++)
                *(float4*)&Vs[j * QS_STRIDE + seg * 32 + 4 * i] = *(const float4*)(src + 4 * i);
        }
        __syncthreads();

        // scores: s[jj] = Q[r,:] . K[sub*16+jj,:]
        float s[16];
#pragma unroll
        for (int jj = 0; jj < 16; jj++) s[jj] = 0.f;
#pragma unroll 4
        for (int d = 0; d < 128; d++) {
            float q = Qs[r * QS_STRIDE + d];
            const float* kp = &Kst[d * KS_STRIDE + sub * 16];
            float4 k0 = *(const float4*)(kp);
            float4 k1 = *(const float4*)(kp + 4);
            float4 k2 = *(const float4*)(kp + 8);
            float4 k3 = *(const float4*)(kp + 12);
            s[0]  += q * k0.x;  s[1]  += q * k0.y;  s[2]  += q * k0.z;  s[3]  += q * k0.w;
            s[4]  += q * k1.x;  s[5]  += q * k1.y;  s[6]  += q * k1.z;  s[7]  += q * k1.w;
            s[8]  += q * k2.x;  s[9]  += q * k2.y;  s[10] += q * k2.z;  s[11] += q * k2.w;
            s[12] += q * k3.x;  s[13] += q * k3.y;  s[14] += q * k3.z;  s[15] += q * k3.w;
        }
        if (kt == qt) {
#pragma unroll
            for (int jj = 0; jj < 16; jj++)
                if (sub * 16 + jj > r) s[jj] = -1e30f;
        }

        // online softmax (4 lanes per row share stats via shfl)
        float tmax = s[0];
#pragma unroll
        for (int jj = 1; jj < 16; jj++) tmax = fmaxf(tmax, s[jj]);
        tmax = fmaxf(tmax, __shfl_xor_sync(0xffffffffu, tmax, 1));
        tmax = fmaxf(tmax, __shfl_xor_sync(0xffffffffu, tmax, 2));
        float newm = fmaxf(m, tmax);
        float corr = __expf(m - newm);
        m = newm;
        float psum = 0.f;
#pragma unroll
        for (int jj = 0; jj < 16; jj++) { s[jj] = __expf(s[jj] - m); psum += s[jj]; }
        psum += __shfl_xor_sync(0xffffffffu, psum, 1);
        psum += __shfl_xor_sync(0xffffffffu, psum, 2);
        l = l * corr + psum;
#pragma unroll
        for (int i = 0; i < 32; i++) o[i] *= corr;

        // share P through smem
        float* pp = &Ps[r * PS_STRIDE + sub * 16];
        *(float4*)(pp)      = make_float4(s[0],  s[1],  s[2],  s[3]);
        *(float4*)(pp + 4)  = make_float4(s[4],  s[5],  s[6],  s[7]);
        *(float4*)(pp + 8)  = make_float4(s[8],  s[9],  s[10], s[11]);
        *(float4*)(pp + 12) = make_float4(s[12], s[13], s[14], s[15]);
        __syncthreads();

        // O[r, sub*32 + c] += sum_j P[r,j] * V[j, sub*32 + c]
#pragma unroll 2
        for (int j = 0; j < 64; j++) {
            float p = Ps[r * PS_STRIDE + j];
            const float* vp = &Vs[j * QS_STRIDE + sub * 32];
#pragma unroll
            for (int i = 0; i < 8; i++) {
                float4 v = *(const float4*)(vp + 4 * i);
                o[4*i+0] += p * v.x;
                o[4*i+1] += p * v.y;
                o[4*i+2] += p * v.z;
                o[4*i+3] += p * v.w;
            }
        }
    }

    // epilogue: normalize, write token-major for o_proj GEMM
    float inv = 1.f / l;
    float* dst = attn + ((size_t)(b * SS + qt * 64 + r)) * (NH * DD) + h * DD + sub * 32;
#pragma unroll
    for (int i = 0; i < 8; i++) {
        float4 v = make_float4(o[4*i+0] * inv, o[4*i+1] * inv, o[4*i+2] * inv, o[4*i+3] * inv);
        *(float4*)(dst + 4 * i) = v;
    }
}

// ---------------- launch ----------------
extern "C" void kernel_launch(void* const* d_in, const int* in_sizes, int n_in,
                              void* d_out, int out_size)
{
    const float* X    = (const float*)d_in[0];   // hidden_states [B,S,HID]
    const float* Wq   = (const float*)d_in[1];   // [HID, NH*D]
    const float* Wk   = (const float*)d_in[2];   // [HID, NKV*D]
    const float* Wv   = (const float*)d_in[3];   // [HID, NKV*D]
    const float* Wo   = (const float*)d_in[4];   // [NH*D, HID]
    const float* cosc = (const float*)d_in[5];   // [S, D]
    const float* sinc = (const float*)d_in[6];   // [S, D]
    // d_in[7] position_ids (= arange, unused), d_in[8] attention_mask (= causal, unused)
    float* out = (float*)d_out;

    float *gq, *gk, *gv, *gQh, *gKhT, *gVh, *gattn;
    cudaGetSymbolAddress((void**)&gq,    g_q);
    cudaGetSymbolAddress((void**)&gk,    g_k);
    cudaGetSymbolAddress((void**)&gv,    g_v);
    cudaGetSymbolAddress((void**)&gQh,   g_Qh);
    cudaGetSymbolAddress((void**)&gKhT,  g_KhT);
    cudaGetSymbolAddress((void**)&gVh,   g_Vh);
    cudaGetSymbolAddress((void**)&gattn, g_attn);

    // QKV projections
    sgemm_kernel<<<dim3(NH*DD/128, TT/128), 256>>>(X, Wq, gq,  TT, NH*DD,  HID);
    sgemm_kernel<<<dim3(NKV*DD/128, TT/128), 256>>>(X, Wk, gk, TT, NKV*DD, HID);
    sgemm_kernel<<<dim3(NKV*DD/128, TT/128), 256>>>(X, Wv, gv, TT, NKV*DD, HID);

    // RoPE + permute
    rope_q_kernel<<<(TT*NH*DD)/256, 256>>>(gq, cosc, sinc, gQh);
    rope_k_kernel<<<(TT*NKV*DD)/256, 256>>>(gk, cosc, sinc, gKhT);
    perm_v_kernel<<<(TT*NKV*DD)/256, 256>>>(gv, gVh);

    // flash attention
    static bool attr_set = false;
    if (!attr_set) {
        cudaFuncSetAttribute(flash_kernel, cudaFuncAttributeMaxDynamicSharedMemorySize,
                             SMEM_FLOATS * (int)sizeof(float));
        attr_set = true;
    }
    flash_kernel<<<dim3(SS/64, NH, BB), 256, SMEM_FLOATS * sizeof(float)>>>(
        gQh, gKhT, gVh, gattn);

    // output projection
    sgemm_kernel<<<dim3(HID/128, TT/128), 256>>>(gattn, Wo, out, TT, HID, NH*DD);
}

// round 3
// speedup vs baseline: 1.3370x; 1.3370x over previous
#include <cuda_runtime.h>
#include <cuda_fp16.h>
#include <stdint.h>
#include <math.h>

// Problem constants
#define BB   2
#define SS   2048
#define HID  4096
#define NH   32
#define NKV  8
#define DD   128
#define TT   (BB*SS)       // 4096 tokens

// ---------------- scratch (device globals) ----------------
__device__ float g_q   [(size_t)TT * HID];
__device__ float g_k   [(size_t)TT * (NKV*DD)];
__device__ float g_v   [(size_t)TT * (NKV*DD)];
__device__ float g_Qh  [(size_t)TT * (NH*DD)];
__device__ float g_KhT [(size_t)TT * (NKV*DD)];
__device__ float g_Vh  [(size_t)TT * (NKV*DD)];
__device__ float g_attn[(size_t)TT * HID];

__device__ __half g_Xhi[(size_t)TT * HID];
__device__ __half g_Xlo[(size_t)TT * HID];
__device__ __half g_Ahi[(size_t)TT * HID];
__device__ __half g_Alo[(size_t)TT * HID];
__device__ __half g_Wqt_hi[(size_t)HID * HID];
__device__ __half g_Wqt_lo[(size_t)HID * HID];
__device__ __half g_Wkt_hi[(size_t)HID * (NKV*DD)];
__device__ __half g_Wkt_lo[(size_t)HID * (NKV*DD)];
__device__ __half g_Wvt_hi[(size_t)HID * (NKV*DD)];
__device__ __half g_Wvt_lo[(size_t)HID * (NKV*DD)];
__device__ __half g_Wot_hi[(size_t)HID * HID];
__device__ __half g_Wot_lo[(size_t)HID * HID];

// ---------------- PTX helpers (baseline features only; NO tcgen05/TMA-a) ----------------
__device__ __forceinline__ uint32_t smem_u32(const void* p) {
    uint32_t a;
    asm("{ .reg .u64 t; cvta.to.shared.u64 t, %1; cvt.u32.u64 %0, t; }" : "=r"(a) : "l"(p));
    return a;
}

#define CP16(dst, src) \
    asm volatile("cp.async.cg.shared.global [%0], [%1], 16;" :: "r"(dst), "l"(src) : "memory")
#define CP_COMMIT() asm volatile("cp.async.commit_group;" ::: "memory")
#define CP_WAIT_0() asm volatile("cp.async.wait_group 0;" ::: "memory")
#define CP_WAIT_1() asm volatile("cp.async.wait_group 1;" ::: "memory")

#define LDM_X4(r0, r1, r2, r3, addr) \
    asm volatile("ldmatrix.sync.aligned.m8n8.x4.shared.b16 {%0,%1,%2,%3}, [%4];" \
        : "=r"(r0), "=r"(r1), "=r"(r2), "=r"(r3) : "r"(addr))

__device__ __forceinline__ void mma16816(float* d, const uint32_t* a, const uint32_t* b) {
    asm volatile("mma.sync.aligned.m16n8k16.row.col.f32.f16.f16.f32 "
        "{%0,%1,%2,%3}, {%4,%5,%6,%7}, {%8,%9}, {%0,%1,%2,%3};"
        : "+f"(d[0]), "+f"(d[1]), "+f"(d[2]), "+f"(d[3])
        : "r"(a[0]), "r"(a[1]), "r"(a[2]), "r"(a[3]), "r"(b[0]), "r"(b[1]));
}

// ---------------- split / transpose prep kernels (fp16 hi/lo) ----------------
__global__ void split_kernel(const float* __restrict__ X,
                             __half* __restrict__ H, __half* __restrict__ L)
{
    size_t i = ((size_t)blockIdx.x * blockDim.x + threadIdx.x) * 4;
    float4 v = *(const float4*)(X + i);
    __align__(8) __half h[4], l[4];
    float vv[4] = {v.x, v.y, v.z, v.w};
#pragma unroll
    for (int j = 0; j < 4; j++) {
        h[j] = __float2half_rn(vv[j]);
        l[j] = __float2half_rn(vv[j] - __half2float(h[j]));
    }
    *(uint2*)(H + i) = *(uint2*)h;
    *(uint2*)(L + i) = *(uint2*)l;
}

// W [Kd, Nd] row-major -> Th/Tl [Nd, Kd] fp16 hi/lo
__global__ void transpose_split_kernel(const float* __restrict__ W,
                                       __half* __restrict__ Th, __half* __restrict__ Tl,
                                       int Kd, int Nd)
{
    __shared__ float tile[32][33];
    int n0 = blockIdx.x * 32, k0 = blockIdx.y * 32;
    int tx = threadIdx.x, ty = threadIdx.y;
#pragma unroll
    for (int i = 0; i < 4; i++)
        tile[ty + 8*i][tx] = W[(size_t)(k0 + ty + 8*i) * Nd + n0 + tx];
    __syncthreads();
#pragma unroll
    for (int i = 0; i < 4; i++) {
        float v = tile[tx][ty + 8*i];
        __half h = __float2half_rn(v);
        __half l = __float2half_rn(v - __half2float(h));
        size_t o = (size_t)(n0 + ty + 8*i) * Kd + k0 + tx;
        Th[o] = h; Tl[o] = l;
    }
}

// ---------------- mma.sync fp16-split GEMM ----------------
// C[M,N] = (Ahi+Alo)[M,K] @ ((Bhi+Blo)[N,K])^T, 3-term: AhBh + AlBh + AhBl.
// Tile 128x128x64, 8 warps (2x4), warp tile 64x32, 3-stage cp.async.
// smem stage: Ah[128][64] Al Bh Bl fp16, SW128 swizzle (chunk ^= row&7).
#define GBM 128
#define GBN 128
#define GBK 64
#define STG_AH 0
#define STG_AL 16384
#define STG_BH 32768
#define STG_BL 49152
#define STG_SZ 65536
#define GEMM_SMEM_TOTAL (3*STG_SZ)

__global__ __launch_bounds__(256, 1) void hgemm3_kernel(
    const __half* __restrict__ Ahi, const __half* __restrict__ Alo,
    const __half* __restrict__ Bhi, const __half* __restrict__ Blo,
    float* __restrict__ C, int M, int N, int K)
{
    extern __shared__ __align__(128) char smem[];
    const uint32_t sbase = smem_u32(smem);
    const int tid = threadIdx.x;
    const int lane = tid & 31;
    const int wid = tid >> 5;
    const int wm = wid >> 2;       // 0..1
    const int wn = wid & 3;        // 0..3

    const size_t arow0 = (size_t)blockIdx.y * GBM;
    const size_t brow0 = (size_t)blockIdx.x * GBN;
    const __half* Ah = Ahi + arow0 * K;
    const __half* Al = Alo + arow0 * K;
    const __half* Bh = Bhi + brow0 * K;
    const __half* Bl = Blo + brow0 * K;

    const int NC = K / GBK;

    // per-thread load coords: 8 iterations cover 128 rows x 8 chunks
    const int lrow = tid >> 3;          // base row (advances +32 per iter)
    const int lc   = tid & 7;           // 16B chunk within row

    auto stage_u32 = [&](int st) { return sbase + st * STG_SZ; };

    // load one stage (A & B tiles, hi & lo)
    #define LOAD_STAGE(st, koff)                                                 \
    do {                                                                         \
        uint32_t s0 = stage_u32(st);                                             \
        _Pragma("unroll")                                                        \
        for (int i = 0; i < 4; i++) {                                            \
            int row = lrow + i * 32;                                             \
            uint32_t off = (uint32_t)(row * 128 + ((lc ^ (row & 7)) << 4));      \
            size_t go = (size_t)row * K + (koff) + lc * 8;                       \
            CP16(s0 + STG_AH + off, Ah + go);                                    \
            CP16(s0 + STG_AL + off, Al + go);                                    \
            CP16(s0 + STG_BH + off, Bh + go);                                    \
            CP16(s0 + STG_BL + off, Bl + go);                                    \
        }                                                                        \
        CP_COMMIT();                                                             \
    } while (0)

    LOAD_STAGE(0, 0);
    LOAD_STAGE(1, GBK);

    float acc[4][4][4];
#pragma unroll
    for (int mt = 0; mt < 4; mt++)
#pragma unroll
        for (int nt = 0; nt < 4; nt++)
#pragma unroll
            for (int j = 0; j < 4; j++) acc[mt][nt][j] = 0.f;

    // precompute lane pieces for ldmatrix addressing
    const int g  = lane >> 3;        // 0..3
    const int r8 = lane & 7;

    for (int c = 0; c < NC; c++) {
        if (c + 1 < NC) { CP_WAIT_1(); } else { CP_WAIT_0(); }
        __syncthreads();
        if (c + 2 < NC) LOAD_STAGE((c + 2) % 3, (c + 2) * GBK);

        const uint32_t sA = stage_u32(c % 3);
        const uint32_t sB = sA + STG_BH;

#pragma unroll
        for (int ks = 0; ks < 4; ks++) {
            // A fragments: 4 m-tiles, hi & lo
            uint32_t ah[4][4], al[4][4];
#pragma unroll
            for (int mt = 0; mt < 4; mt++) {
                int arow = wm * 64 + mt * 16 + (g & 1) * 8 + r8;
                int kc = ks * 2 + (g >> 1);
                uint32_t addr = sA + (uint32_t)(arow * 128 + ((kc ^ (arow & 7)) << 4));
                LDM_X4(ah[mt][0], ah[mt][1], ah[mt][2], ah[mt][3], addr);
                LDM_X4(al[mt][0], al[mt][1], al[mt][2], al[mt][3], addr + STG_AL);
            }
            // B fragments: 4 n-tiles (two ldmatrix.x4, each covers 2 n-tiles)
            uint32_t bh[4][2], bl[4][2];
#pragma unroll
            for (int pr = 0; pr < 2; pr++) {
                int bn = wn * 32 + pr * 16 + (g >> 1) * 8 + r8;
                int kc = ks * 2 + (g & 1);
                uint32_t addr = sB + (uint32_t)(bn * 128 + ((kc ^ (bn & 7)) << 4));
                uint32_t t0, t1, t2, t3;
                LDM_X4(t0, t1, t2, t3, addr);
                bh[pr*2][0] = t0; bh[pr*2][1] = t1; bh[pr*2+1][0] = t2; bh[pr*2+1][1] = t3;
                LDM_X4(t0, t1, t2, t3, addr + 16384);   // BL - BH = 16384
                bl[pr*2][0] = t0; bl[pr*2][1] = t1; bl[pr*2+1][0] = t2; bl[pr*2+1][1] = t3;
            }
            // 3-term MMAs
#pragma unroll
            for (int mt = 0; mt < 4; mt++)
#pragma unroll
                for (int nt = 0; nt < 4; nt++) {
                    mma16816(acc[mt][nt], ah[mt], bh[nt]);
                    mma16816(acc[mt][nt], al[mt], bh[nt]);
                    mma16816(acc[mt][nt], ah[mt], bl[nt]);
                }
        }
        __syncthreads();
    }

    // epilogue
    const int er = lane >> 2;          // 0..7
    const int ec = (lane & 3) * 2;
#pragma unroll
    for (int mt = 0; mt < 4; mt++) {
        size_t m0 = arow0 + wm * 64 + mt * 16 + er;
#pragma unroll
        for (int nt = 0; nt < 4; nt++) {
            size_t n0 = brow0 + wn * 32 + nt * 8 + ec;
            float2 v0 = make_float2(acc[mt][nt][0], acc[mt][nt][1]);
            float2 v1 = make_float2(acc[mt][nt][2], acc[mt][nt][3]);
            *(float2*)(C + m0 * N + n0)       = v0;
            *(float2*)(C + (m0 + 8) * N + n0) = v1;
        }
    }
    #undef LOAD_STAGE
}

// ---------------- RoPE + permute kernels ----------------
__global__ void rope_q_kernel(const float* __restrict__ cq,
                              const float* __restrict__ cosc,
                              const float* __restrict__ sinc,
                              float* __restrict__ Qh)
{
    int idx = blockIdx.x * blockDim.x + threadIdx.x;
    int d = idx & 127;
    int h = (idx >> 7) & 31;
    int t = idx >> 12;
    int s = t & (SS - 1);
    int b = t >> 11;
    float v  = cq[idx];
    float vp = cq[idx ^ 64];
    float rot = (d < 64) ? -vp : vp;
    float c  = cosc[s * DD + d];
    float sn = sinc[s * DD + d];
    const float scale = 0.08838834764831845f;  // 1/sqrt(128)
    Qh[(((size_t)(b * NH + h)) * SS + s) * DD + d] = (v * c + rot * sn) * scale;
}

__global__ void rope_k_kernel(const float* __restrict__ ck,
                              const float* __restrict__ cosc,
                              const float* __restrict__ sinc,
                              float* __restrict__ KhT)
{
    int idx = blockIdx.x * blockDim.x + threadIdx.x;
    int d  = idx & 127;
    int kh = (idx >> 7) & 7;
    int t  = idx >> 10;
    int s = t & (SS - 1);
    int b = t >> 11;
    float v  = ck[idx];
    float vp = ck[idx ^ 64];
    float rot = (d < 64) ? -vp : vp;
    float c  = cosc[s * DD + d];
    float sn = sinc[s * DD + d];
    KhT[(((size_t)(b * NKV + kh)) * DD + d) * SS + s] = v * c + rot * sn;
}

__global__ void perm_v_kernel(const float* __restrict__ cv, float* __restrict__ Vh)
{
    int idx = blockIdx.x * blockDim.x + threadIdx.x;
    int d  = idx & 127;
    int kh = (idx >> 7) & 7;
    int t  = idx >> 10;
    int s = t & (SS - 1);
    int b = t >> 11;
    Vh[(((size_t)(b * NKV + kh)) * SS + s) * DD + d] = cv[idx];
}

// ---------------- Flash attention (fp32, causal, GQA) ----------------
#define QS_STRIDE 132
#define KS_STRIDE 68
#define PS_STRIDE 68
#define SMEM_FLOATS (64*QS_STRIDE + 128*KS_STRIDE + 64*QS_STRIDE + 64*PS_STRIDE)

__global__ __launch_bounds__(256) void flash_kernel(
    const float* __restrict__ Qh, const float* __restrict__ KhT,
    const float* __restrict__ Vh, float* __restrict__ attn)
{
    extern __shared__ float sm[];
    float* Qs  = sm;
    float* Kst = Qs + 64 * QS_STRIDE;
    float* Vs  = Kst + 128 * KS_STRIDE;
    float* Ps  = Vs + 64 * QS_STRIDE;

    int qt = blockIdx.x;
    int h  = blockIdx.y;
    int b  = blockIdx.z;
    int kh = h >> 2;
    int tid = threadIdx.x;
    int r   = tid >> 2;
    int sub = tid & 3;

    {
        int j = tid >> 2, seg = tid & 3;
        const float* src = Qh + (((size_t)(b * NH + h)) * SS + qt * 64 + j) * DD + seg * 32;
#pragma unroll
        for (int i = 0; i < 8; i++)
            *(float4*)&Qs[j * QS_STRIDE + seg * 32 + 4 * i] = *(const float4*)(src + 4 * i);
    }

    float m = -1e30f, l = 0.f;
    float o[32];
#pragma unroll
    for (int i = 0; i < 32; i++) o[i] = 0.f;

    for (int kt = 0; kt <= qt; kt++) {
        __syncthreads();
        {
            int d = tid >> 1, jseg = tid & 1;
            const float* src = KhT + (((size_t)(b * NKV + kh)) * DD + d) * SS + kt * 64 + jseg * 32;
#pragma unroll
            for (int i = 0; i < 8; i++)
                *(float4*)&Kst[d * KS_STRIDE + jseg * 32 + 4 * i] = *(const float4*)(src + 4 * i);
        }
        {
            int j = tid >> 2, seg = tid & 3;
            const float* src = Vh + (((size_t)(b * NKV + kh)) * SS + kt * 64 + j) * DD + seg * 32;
#pragma unroll
            for (int i = 0; i < 8; i++)
                *(float4*)&Vs[j * QS_STRIDE + seg * 32 + 4 * i] = *(const float4*)(src + 4 * i);
        }
        __syncthreads();

        float s[16];
#pragma unroll
        for (int jj = 0; jj < 16; jj++) s[jj] = 0.f;
#pragma unroll 4
        for (int d = 0; d < 128; d++) {
            float q = Qs[r * QS_STRIDE + d];
            const float* kp = &Kst[d * KS_STRIDE + sub * 16];
            float4 k0 = *(const float4*)(kp);
            float4 k1 = *(const float4*)(kp + 4);
            float4 k2 = *(const float4*)(kp + 8);
            float4 k3 = *(const float4*)(kp + 12);
            s[0]  += q * k0.x;  s[1]  += q * k0.y;  s[2]  += q * k0.z;  s[3]  += q * k0.w;
            s[4]  += q * k1.x;  s[5]  += q * k1.y;  s[6]  += q * k1.z;  s[7]  += q * k1.w;
            s[8]  += q * k2.x;  s[9]  += q * k2.y;  s[10] += q * k2.z;  s[11] += q * k2.w;
            s[12] += q * k3.x;  s[13] += q * k3.y;  s[14] += q * k3.z;  s[15] += q * k3.w;
        }
        if (kt == qt) {
#pragma unroll
            for (int jj = 0; jj < 16; jj++)
                if (sub * 16 + jj > r) s[jj] = -1e30f;
        }

        float tmax = s[0];
#pragma unroll
        for (int jj = 1; jj < 16; jj++) tmax = fmaxf(tmax, s[jj]);
        tmax = fmaxf(tmax, __shfl_xor_sync(0xffffffffu, tmax, 1));
        tmax = fmaxf(tmax, __shfl_xor_sync(0xffffffffu, tmax, 2));
        float newm = fmaxf(m, tmax);
        float corr = __expf(m - newm);
        m = newm;
        float psum = 0.f;
#pragma unroll
        for (int jj = 0; jj < 16; jj++) { s[jj] = __expf(s[jj] - m); psum += s[jj]; }
        psum += __shfl_xor_sync(0xffffffffu, psum, 1);
        psum += __shfl_xor_sync(0xffffffffu, psum, 2);
        l = l * corr + psum;
#pragma unroll
        for (int i = 0; i < 32; i++) o[i] *= corr;

        float* pp = &Ps[r * PS_STRIDE + sub * 16];
        *(float4*)(pp)      = make_float4(s[0],  s[1],  s[2],  s[3]);
        *(float4*)(pp + 4)  = make_float4(s[4],  s[5],  s[6],  s[7]);
        *(float4*)(pp + 8)  = make_float4(s[8],  s[9],  s[10], s[11]);
        *(float4*)(pp + 12) = make_float4(s[12], s[13], s[14], s[15]);
        __syncthreads();

#pragma unroll 2
        for (int j = 0; j < 64; j++) {
            float p = Ps[r * PS_STRIDE + j];
            const float* vp = &Vs[j * QS_STRIDE + sub * 32];
#pragma unroll
            for (int i = 0; i < 8; i++) {
                float4 v = *(const float4*)(vp + 4 * i);
                o[4*i+0] += p * v.x;
                o[4*i+1] += p * v.y;
                o[4*i+2] += p * v.z;
                o[4*i+3] += p * v.w;
            }
        }
    }

    float inv = 1.f / l;
    float* dst = attn + ((size_t)(b * SS + qt * 64 + r)) * (NH * DD) + h * DD + sub * 32;
#pragma unroll
    for (int i = 0; i < 8; i++) {
        float4 v = make_float4(o[4*i+0] * inv, o[4*i+1] * inv, o[4*i+2] * inv, o[4*i+3] * inv);
        *(float4*)(dst + 4 * i) = v;
    }
}

// ---------------- launch ----------------
extern "C" void kernel_launch(void* const* d_in, const int* in_sizes, int n_in,
                              void* d_out, int out_size)
{
    const float* X    = (const float*)d_in[0];
    const float* Wq   = (const float*)d_in[1];
    const float* Wk   = (const float*)d_in[2];
    const float* Wv   = (const float*)d_in[3];
    const float* Wo   = (const float*)d_in[4];
    const float* cosc = (const float*)d_in[5];
    const float* sinc = (const float*)d_in[6];
    float* out = (float*)d_out;

    float *gq, *gk, *gv, *gQh, *gKhT, *gVh, *gattn;
    __half *gXhi, *gXlo, *gAhi, *gAlo;
    __half *gWqh, *gWql, *gWkh, *gWkl, *gWvh, *gWvl, *gWoh, *gWol;
    cudaGetSymbolAddress((void**)&gq,    g_q);
    cudaGetSymbolAddress((void**)&gk,    g_k);
    cudaGetSymbolAddress((void**)&gv,    g_v);
    cudaGetSymbolAddress((void**)&gQh,   g_Qh);
    cudaGetSymbolAddress((void**)&gKhT,  g_KhT);
    cudaGetSymbolAddress((void**)&gVh,   g_Vh);
    cudaGetSymbolAddress((void**)&gattn, g_attn);
    cudaGetSymbolAddress((void**)&gXhi,  g_Xhi);
    cudaGetSymbolAddress((void**)&gXlo,  g_Xlo);
    cudaGetSymbolAddress((void**)&gAhi,  g_Ahi);
    cudaGetSymbolAddress((void**)&gAlo,  g_Alo);
    cudaGetSymbolAddress((void**)&gWqh,  g_Wqt_hi);
    cudaGetSymbolAddress((void**)&gWql,  g_Wqt_lo);
    cudaGetSymbolAddress((void**)&gWkh,  g_Wkt_hi);
    cudaGetSymbolAddress((void**)&gWkl,  g_Wkt_lo);
    cudaGetSymbolAddress((void**)&gWvh,  g_Wvt_hi);
    cudaGetSymbolAddress((void**)&gWvl,  g_Wvt_lo);
    cudaGetSymbolAddress((void**)&gWoh,  g_Wot_hi);
    cudaGetSymbolAddress((void**)&gWol,  g_Wot_lo);

    static bool attr_set = false;
    if (!attr_set) {
        cudaFuncSetAttribute(hgemm3_kernel, cudaFuncAttributeMaxDynamicSharedMemorySize,
                             GEMM_SMEM_TOTAL);
        cudaFuncSetAttribute(flash_kernel, cudaFuncAttributeMaxDynamicSharedMemorySize,
                             SMEM_FLOATS * (int)sizeof(float));
        attr_set = true;
    }

    // split X into fp16 hi/lo
    split_kernel<<<(TT*HID)/1024, 256>>>(X, gXhi, gXlo);
    // transpose + split weights: [K,N] -> [N,K]
    transpose_split_kernel<<<dim3(HID/32, HID/32), dim3(32, 8)>>>(Wq, gWqh, gWql, HID, HID);
    transpose_split_kernel<<<dim3((NKV*DD)/32, HID/32), dim3(32, 8)>>>(Wk, gWkh, gWkl, HID, NKV*DD);
    transpose_split_kernel<<<dim3((NKV*DD)/32, HID/32), dim3(32, 8)>>>(Wv, gWvh, gWvl, HID, NKV*DD);
    transpose_split_kernel<<<dim3(HID/32, HID/32), dim3(32, 8)>>>(Wo, gWoh, gWol, HID, HID);

    // QKV projections on tensor cores (mma.sync)
    hgemm3_kernel<<<dim3(HID/GBN, TT/GBM), 256, GEMM_SMEM_TOTAL>>>(
        gXhi, gXlo, gWqh, gWql, gq, TT, HID, HID);
    hgemm3_kernel<<<dim3((NKV*DD)/GBN, TT/GBM), 256, GEMM_SMEM_TOTAL>>>(
        gXhi, gXlo, gWkh, gWkl, gk, TT, NKV*DD, HID);
    hgemm3_kernel<<<dim3((NKV*DD)/GBN, TT/GBM), 256, GEMM_SMEM_TOTAL>>>(
        gXhi, gXlo, gWvh, gWvl, gv, TT, NKV*DD, HID);

    // RoPE + permute
    rope_q_kernel<<<(TT*NH*DD)/256, 256>>>(gq, cosc, sinc, gQh);
    rope_k_kernel<<<(TT*NKV*DD)/256, 256>>>(gk, cosc, sinc, gKhT);
    perm_v_kernel<<<(TT*NKV*DD)/256, 256>>>(gv, gVh);

    // flash attention (fp32)
    flash_kernel<<<dim3(SS/64, NH, BB), 256, SMEM_FLOATS * sizeof(float)>>>(
        gQh, gKhT, gVh, gattn);

    // split attention output, then o_proj on tensor cores
    split_kernel<<<(TT*HID)/1024, 256>>>(gattn, gAhi, gAlo);
    hgemm3_kernel<<<dim3(HID/GBN, TT/GBM), 256, GEMM_SMEM_TOTAL>>>(
        gAhi, gAlo, gWoh, gWol, out, TT, HID, HID);
}

// round 4
// speedup vs baseline: 6.7622x; 5.0576x over previous
#include <cuda_runtime.h>
#include <cuda_fp16.h>
#include <stdint.h>
#include <math.h>

// Problem constants
#define BB   2
#define SS   2048
#define HID  4096
#define NH   32
#define NKV  8
#define DD   128
#define TT   (BB*SS)       // 4096 tokens

// ---------------- scratch (device globals) ----------------
__device__ float g_q   [(size_t)TT * HID];
__device__ float g_k   [(size_t)TT * (NKV*DD)];
__device__ float g_v   [(size_t)TT * (NKV*DD)];
__device__ float g_attn[(size_t)TT * HID];

__device__ __half g_Xhi[(size_t)TT * HID];
__device__ __half g_Xlo[(size_t)TT * HID];
__device__ __half g_Ahi[(size_t)TT * HID];
__device__ __half g_Alo[(size_t)TT * HID];
__device__ __half g_Wqt_hi[(size_t)HID * HID];
__device__ __half g_Wqt_lo[(size_t)HID * HID];
__device__ __half g_Wkt_hi[(size_t)HID * (NKV*DD)];
__device__ __half g_Wkt_lo[(size_t)HID * (NKV*DD)];
__device__ __half g_Wvt_hi[(size_t)HID * (NKV*DD)];
__device__ __half g_Wvt_lo[(size_t)HID * (NKV*DD)];
__device__ __half g_Wot_hi[(size_t)HID * HID];
__device__ __half g_Wot_lo[(size_t)HID * HID];

// flash operands (fp16 hi/lo)
__device__ __half g_Qfhi[(size_t)TT * (NH*DD)];
__device__ __half g_Qflo[(size_t)TT * (NH*DD)];
__device__ __half g_Kfhi[(size_t)TT * (NKV*DD)];
__device__ __half g_Kflo[(size_t)TT * (NKV*DD)];
__device__ __half g_VThi[(size_t)TT * (NKV*DD)];   // [b,kh,d,s]
__device__ __half g_VTlo[(size_t)TT * (NKV*DD)];

// ---------------- PTX helpers (baseline features only) ----------------
__device__ __forceinline__ uint32_t smem_u32(const void* p) {
    uint32_t a;
    asm("{ .reg .u64 t; cvta.to.shared.u64 t, %1; cvt.u32.u64 %0, t; }" : "=r"(a) : "l"(p));
    return a;
}

#define CP16(dst, src) \
    asm volatile("cp.async.cg.shared.global [%0], [%1], 16;" :: "r"(dst), "l"(src) : "memory")
#define CP_COMMIT() asm volatile("cp.async.commit_group;" ::: "memory")
#define CP_WAIT_0() asm volatile("cp.async.wait_group 0;" ::: "memory")
#define CP_WAIT_1() asm volatile("cp.async.wait_group 1;" ::: "memory")

#define LDM_X4(r0, r1, r2, r3, addr) \
    asm volatile("ldmatrix.sync.aligned.m8n8.x4.shared.b16 {%0,%1,%2,%3}, [%4];" \
        : "=r"(r0), "=r"(r1), "=r"(r2), "=r"(r3) : "r"(addr))

__device__ __forceinline__ void mma16816(float* d, const uint32_t* a, const uint32_t* b) {
    asm volatile("mma.sync.aligned.m16n8k16.row.col.f32.f16.f16.f32 "
        "{%0,%1,%2,%3}, {%4,%5,%6,%7}, {%8,%9}, {%0,%1,%2,%3};"
        : "+f"(d[0]), "+f"(d[1]), "+f"(d[2]), "+f"(d[3])
        : "r"(a[0]), "r"(a[1]), "r"(a[2]), "r"(a[3]), "r"(b[0]), "r"(b[1]));
}

__device__ __forceinline__ float ex2(float x) {
    float r; asm("ex2.approx.f32 %0, %1;" : "=f"(r) : "f"(x)); return r;
}
__device__ __forceinline__ uint32_t f22u(float a, float b) {
    __half2 h = __floats2half2_rn(a, b);
    return *(uint32_t*)&h;
}

// ---------------- split / transpose prep kernels (fp16 hi/lo) ----------------
__global__ void split_kernel(const float* __restrict__ X,
                             __half* __restrict__ H, __half* __restrict__ L)
{
    size_t i = ((size_t)blockIdx.x * blockDim.x + threadIdx.x) * 4;
    float4 v = *(const float4*)(X + i);
    __align__(8) __half h[4], l[4];
    float vv[4] = {v.x, v.y, v.z, v.w};
#pragma unroll
    for (int j = 0; j < 4; j++) {
        h[j] = __float2half_rn(vv[j]);
        l[j] = __float2half_rn(vv[j] - __half2float(h[j]));
    }
    *(uint2*)(H + i) = *(uint2*)h;
    *(uint2*)(L + i) = *(uint2*)l;
}

// W [Kd, Nd] row-major -> Th/Tl [Nd, Kd] fp16 hi/lo
__global__ void transpose_split_kernel(const float* __restrict__ W,
                                       __half* __restrict__ Th, __half* __restrict__ Tl,
                                       int Kd, int Nd)
{
    __shared__ float tile[32][33];
    int n0 = blockIdx.x * 32, k0 = blockIdx.y * 32;
    int tx = threadIdx.x, ty = threadIdx.y;
#pragma unroll
    for (int i = 0; i < 4; i++)
        tile[ty + 8*i][tx] = W[(size_t)(k0 + ty + 8*i) * Nd + n0 + tx];
    __syncthreads();
#pragma unroll
    for (int i = 0; i < 4; i++) {
        float v = tile[tx][ty + 8*i];
        __half h = __float2half_rn(v);
        __half l = __float2half_rn(v - __half2float(h));
        size_t o = (size_t)(n0 + ty + 8*i) * Kd + k0 + tx;
        Th[o] = h; Tl[o] = l;
    }
}

// ---------------- mma.sync fp16-split GEMM (unchanged from R3, proven) ----------------
#define GBM 128
#define GBN 128
#define GBK 64
#define STG_AH 0
#define STG_AL 16384
#define STG_BH 32768
#define STG_BL 49152
#define STG_SZ 65536
#define GEMM_SMEM_TOTAL (3*STG_SZ)

__global__ __launch_bounds__(256, 1) void hgemm3_kernel(
    const __half* __restrict__ Ahi, const __half* __restrict__ Alo,
    const __half* __restrict__ Bhi, const __half* __restrict__ Blo,
    float* __restrict__ C, int M, int N, int K)
{
    extern __shared__ __align__(128) char smem[];
    const uint32_t sbase = smem_u32(smem);
    const int tid = threadIdx.x;
    const int lane = tid & 31;
    const int wid = tid >> 5;
    const int wm = wid >> 2;
    const int wn = wid & 3;

    const size_t arow0 = (size_t)blockIdx.y * GBM;
    const size_t brow0 = (size_t)blockIdx.x * GBN;
    const __half* Ah = Ahi + arow0 * K;
    const __half* Al = Alo + arow0 * K;
    const __half* Bh = Bhi + brow0 * K;
    const __half* Bl = Blo + brow0 * K;

    const int NC = K / GBK;
    const int lrow = tid >> 3;
    const int lc   = tid & 7;

    auto stage_u32 = [&](int st) { return sbase + st * STG_SZ; };

    #define LOAD_STAGE(st, koff)                                                 \
    do {                                                                         \
        uint32_t s0 = stage_u32(st);                                             \
        _Pragma("unroll")                                                        \
        for (int i = 0; i < 4; i++) {                                            \
            int row = lrow + i * 32;                                             \
            uint32_t off = (uint32_t)(row * 128 + ((lc ^ (row & 7)) << 4));      \
            size_t go = (size_t)row * K + (koff) + lc * 8;                       \
            CP16(s0 + STG_AH + off, Ah + go);                                    \
            CP16(s0 + STG_AL + off, Al + go);                                    \
            CP16(s0 + STG_BH + off, Bh + go);                                    \
            CP16(s0 + STG_BL + off, Bl + go);                                    \
        }                                                                        \
        CP_COMMIT();                                                             \
    } while (0)

    LOAD_STAGE(0, 0);
    LOAD_STAGE(1, GBK);

    float acc[4][4][4];
#pragma unroll
    for (int mt = 0; mt < 4; mt++)
#pragma unroll
        for (int nt = 0; nt < 4; nt++)
#pragma unroll
            for (int j = 0; j < 4; j++) acc[mt][nt][j] = 0.f;

    const int g  = lane >> 3;
    const int r8 = lane & 7;

    for (int c = 0; c < NC; c++) {
        if (c + 1 < NC) { CP_WAIT_1(); } else { CP_WAIT_0(); }
        __syncthreads();
        if (c + 2 < NC) LOAD_STAGE((c + 2) % 3, (c + 2) * GBK);

        const uint32_t sA = stage_u32(c % 3);
        const uint32_t sB = sA + STG_BH;

#pragma unroll
        for (int ks = 0; ks < 4; ks++) {
            uint32_t ah[4][4], al[4][4];
#pragma unroll
            for (int mt = 0; mt < 4; mt++) {
                int arow = wm * 64 + mt * 16 + (g & 1) * 8 + r8;
                int kc = ks * 2 + (g >> 1);
                uint32_t addr = sA + (uint32_t)(arow * 128 + ((kc ^ (arow & 7)) << 4));
                LDM_X4(ah[mt][0], ah[mt][1], ah[mt][2], ah[mt][3], addr);
                LDM_X4(al[mt][0], al[mt][1], al[mt][2], al[mt][3], addr + STG_AL);
            }
            uint32_t bh[4][2], bl[4][2];
#pragma unroll
            for (int pr = 0; pr < 2; pr++) {
                int bn = wn * 32 + pr * 16 + (g >> 1) * 8 + r8;
                int kc = ks * 2 + (g & 1);
                uint32_t addr = sB + (uint32_t)(bn * 128 + ((kc ^ (bn & 7)) << 4));
                uint32_t t0, t1, t2, t3;
                LDM_X4(t0, t1, t2, t3, addr);
                bh[pr*2][0] = t0; bh[pr*2][1] = t1; bh[pr*2+1][0] = t2; bh[pr*2+1][1] = t3;
                LDM_X4(t0, t1, t2, t3, addr + 16384);
                bl[pr*2][0] = t0; bl[pr*2][1] = t1; bl[pr*2+1][0] = t2; bl[pr*2+1][1] = t3;
            }
#pragma unroll
            for (int mt = 0; mt < 4; mt++)
#pragma unroll
                for (int nt = 0; nt < 4; nt++) {
                    mma16816(acc[mt][nt], ah[mt], bh[nt]);
                    mma16816(acc[mt][nt], al[mt], bh[nt]);
                    mma16816(acc[mt][nt], ah[mt], bl[nt]);
                }
        }
        __syncthreads();
    }

    const int er = lane >> 2;
    const int ec = (lane & 3) * 2;
#pragma unroll
    for (int mt = 0; mt < 4; mt++) {
        size_t m0 = arow0 + wm * 64 + mt * 16 + er;
#pragma unroll
        for (int nt = 0; nt < 4; nt++) {
            size_t n0 = brow0 + wn * 32 + nt * 8 + ec;
            float2 v0 = make_float2(acc[mt][nt][0], acc[mt][nt][1]);
            float2 v1 = make_float2(acc[mt][nt][2], acc[mt][nt][3]);
            *(float2*)(C + m0 * N + n0)       = v0;
            *(float2*)(C + (m0 + 8) * N + n0) = v1;
        }
    }
    #undef LOAD_STAGE
}

// ---------------- RoPE kernels -> fp16 hi/lo ----------------
// Q scale folds 1/sqrt(D) AND log2(e) so flash uses exp2 directly.
#define QSCALE 0.12751744951953698f

__global__ void rope_q_f16(const float* __restrict__ cq,
                           const float* __restrict__ cosc,
                           const float* __restrict__ sinc,
                           __half* __restrict__ Qhi, __half* __restrict__ Qlo)
{
    int idx = blockIdx.x * blockDim.x + threadIdx.x;
    int d = idx & 127;
    int h = (idx >> 7) & 31;
    int t = idx >> 12;
    int s = t & (SS - 1);
    int b = t >> 11;
    float v  = cq[idx];
    float vp = cq[idx ^ 64];
    float rot = (d < 64) ? -vp : vp;
    float c  = cosc[s * DD + d];
    float sn = sinc[s * DD + d];
    float val = (v * c + rot * sn) * QSCALE;
    __half hi = __float2half_rn(val);
    __half lo = __float2half_rn(val - __half2float(hi));
    size_t o = (((size_t)(b * NH + h)) * SS + s) * DD + d;
    Qhi[o] = hi; Qlo[o] = lo;
}

__global__ void rope_k_f16(const float* __restrict__ ck,
                           const float* __restrict__ cosc,
                           const float* __restrict__ sinc,
                           __half* __restrict__ Khi, __half* __restrict__ Klo)
{
    int idx = blockIdx.x * blockDim.x + threadIdx.x;
    int d  = idx & 127;
    int kh = (idx >> 7) & 7;
    int t  = idx >> 10;
    int s = t & (SS - 1);
    int b = t >> 11;
    float v  = ck[idx];
    float vp = ck[idx ^ 64];
    float rot = (d < 64) ? -vp : vp;
    float c  = cosc[s * DD + d];
    float sn = sinc[s * DD + d];
    float val = v * c + rot * sn;
    __half hi = __float2half_rn(val);
    __half lo = __float2half_rn(val - __half2float(hi));
    size_t o = (((size_t)(b * NKV + kh)) * SS + s) * DD + d;
    Khi[o] = hi; Klo[o] = lo;
}

// V [token][kh*128+d] fp32 -> VT [b,kh,d,s] fp16 hi/lo
__global__ void transpose_v_f16(const float* __restrict__ v,
                                __half* __restrict__ VThi, __half* __restrict__ VTlo)
{
    __shared__ float tile[32][33];
    int s0 = blockIdx.x * 32;
    int d0 = blockIdx.y * 32;
    int bk = blockIdx.z;              // b*NKV + kh
    int b = bk >> 3, kh = bk & 7;
    int tx = threadIdx.x, ty = threadIdx.y;
#pragma unroll
    for (int i = 0; i < 4; i++) {
        int sj = ty + i * 8;
        tile[sj][tx] = v[((size_t)(b * SS + s0 + sj)) * (NKV*DD) + kh * DD + d0 + tx];
    }
    __syncthreads();
#pragma unroll
    for (int i = 0; i < 4; i++) {
        int dj = ty + i * 8;
        float val = tile[tx][dj];
        __half hi = __float2half_rn(val);
        __half lo = __float2half_rn(val - __half2float(hi));
        size_t o = ((size_t)bk * DD + d0 + dj) * SS + s0 + tx;
        VThi[o] = hi; VTlo[o] = lo;
    }
}

// ---------------- Flash attention (mma.sync fp16 split) ----------------
// CTA: 128 q-rows of one (b,h); 8 warps, m16 per warp. KV tiles of 64 keys,
// double-buffered. QK: 3-term (QhKh + QlKh + QhKl). PV: 2-term (PhVh + PhVl).
// Q/K rows are 256B (128 d * fp16): swizzle OFF256. VT rows are 128B: OFF128.
#define FQ_HI 0
#define FQ_LO 32768
#define FSTG0 65536
#define FK_HI 0
#define FK_LO 16384
#define FV_HI 32768
#define FV_LO 49152
#define FSTG_SZ 65536
#define FLASH_SMEM (FSTG0 + 2*FSTG_SZ)   // 196608

// 256B-row swizzle: conflict-free ldmatrix over 8 consecutive rows
__device__ __forceinline__ uint32_t off256(int r, int kc) {
    return (uint32_t)(r * 256 + (((kc & 7) ^ (r & 7)) << 4) + ((kc >> 3) << 7));
}
__device__ __forceinline__ uint32_t off128(int r, int ck) {
    return (uint32_t)(r * 128 + ((ck ^ (r & 7)) << 4));
}

__global__ __launch_bounds__(256, 1) void flash_mma_kernel(
    const __half* __restrict__ Qhi, const __half* __restrict__ Qlo,
    const __half* __restrict__ Khi, const __half* __restrict__ Klo,
    const __half* __restrict__ VThi, const __half* __restrict__ VTlo,
    float* __restrict__ attn)
{
    extern __shared__ __align__(128) char smf[];
    const uint32_t sb = smem_u32(smf);
    const int qblk = blockIdx.x;
    const int h    = blockIdx.y;
    const int b    = blockIdx.z;
    const int kh   = h >> 2;
    const size_t bh  = (size_t)(b * NH + h);
    const size_t bkv = (size_t)(b * NKV + kh);
    const int tid = threadIdx.x, lane = tid & 31, w = tid >> 5;
    const int q0 = qblk * 128;
    const int g  = lane >> 3;
    const int r8 = lane & 7;

    // KV tile loader: 1024 chunks K (hi+lo) + 1024 chunks VT (hi+lo), 16/thread
    #define LOAD_KV(stgof, ktv)                                                   \
    do {                                                                          \
        _Pragma("unroll")                                                         \
        for (int i = 0; i < 4; i++) {                                             \
            int idx = tid + i * 256;                                              \
            int key = idx >> 4, kc = idx & 15;                                    \
            uint32_t so = off256(key, kc);                                        \
            size_t gk = (bkv * SS + (size_t)(ktv) * 64 + key) * DD + kc * 8;      \
            CP16(sb + (stgof) + FK_HI + so, Khi + gk);                            \
            CP16(sb + (stgof) + FK_LO + so, Klo + gk);                            \
            int dd = idx >> 3, ck = idx & 7;                                      \
            uint32_t so2 = off128(dd, ck);                                        \
            size_t gv = (bkv * DD + dd) * SS + (size_t)(ktv) * 64 + ck * 8;       \
            CP16(sb + (stgof) + FV_HI + so2, VThi + gv);                          \
            CP16(sb + (stgof) + FV_LO + so2, VTlo + gv);                          \
        }                                                                         \
        CP_COMMIT();                                                              \
    } while (0)

    // prologue: Q tile + KV tile 0
#pragma unroll
    for (int i = 0; i < 8; i++) {
        int idx = tid + i * 256;
        int q = idx >> 4, kc = idx & 15;
        uint32_t so = off256(q, kc);
        size_t go = (bh * SS + q0 + q) * DD + kc * 8;
        CP16(sb + FQ_HI + so, Qhi + go);
        CP16(sb + FQ_LO + so, Qlo + go);
    }
    CP_COMMIT();
    LOAD_KV(FSTG0, 0);
    CP_WAIT_0();
    __syncthreads();

    // Q fragments to registers (persistent)
    uint32_t qh[8][4], ql[8][4];
#pragma unroll
    for (int ks = 0; ks < 8; ks++) {
        int qr = w * 16 + (g & 1) * 8 + r8;
        int kc = ks * 2 + (g >> 1);
        uint32_t ad = sb + off256(qr, kc);
        LDM_X4(qh[ks][0], qh[ks][1], qh[ks][2], qh[ks][3], ad + FQ_HI);
        LDM_X4(ql[ks][0], ql[ks][1], ql[ks][2], ql[ks][3], ad + FQ_LO);
    }

    float o[16][4];
#pragma unroll
    for (int nt = 0; nt < 16; nt++)
#pragma unroll
        for (int j = 0; j < 4; j++) o[nt][j] = 0.f;
    float m0 = -1e30f, m1 = -1e30f, l0 = 0.f, l1 = 0.f;

    const int last = 2 * qblk + 1;
    for (int kt = 0; kt <= last; kt++) {
        if (kt < last) { LOAD_KV(FSTG0 + ((kt + 1) & 1) * FSTG_SZ, kt + 1); CP_WAIT_1(); }
        else           { CP_WAIT_0(); }
        __syncthreads();

        const uint32_t stg = sb + FSTG0 + (kt & 1) * FSTG_SZ;
        const bool skip = (kt * 64) > (q0 + w * 16 + 15);   // warp-uniform
        if (!skip) {
            // ---- S = Q K^T (3-term) ----
            float s[8][4];
#pragma unroll
            for (int nt = 0; nt < 8; nt++)
#pragma unroll
                for (int j = 0; j < 4; j++) s[nt][j] = 0.f;

#pragma unroll
            for (int ks = 0; ks < 8; ks++) {
#pragma unroll
                for (int ntp = 0; ntp < 4; ntp++) {
                    int bn = ntp * 16 + (g >> 1) * 8 + r8;
                    int kc = ks * 2 + (g & 1);
                    uint32_t ad = stg + off256(bn, kc);
                    uint32_t t0, t1, t2, t3;
                    LDM_X4(t0, t1, t2, t3, ad + FK_HI);
                    uint32_t u0, u1, u2, u3;
                    LDM_X4(u0, u1, u2, u3, ad + FK_LO);
                    uint32_t bh0[2] = {t0, t1}, bh1[2] = {t2, t3};
                    uint32_t bl0[2] = {u0, u1}, bl1[2] = {u2, u3};
                    mma16816(s[2*ntp],   qh[ks], bh0);
                    mma16816(s[2*ntp],   ql[ks], bh0);
                    mma16816(s[2*ntp],   qh[ks], bl0);
                    mma16816(s[2*ntp+1], qh[ks], bh1);
                    mma16816(s[2*ntp+1], ql[ks], bh1);
                    mma16816(s[2*ntp+1], qh[ks], bl1);
                }
            }

            // ---- causal mask (diagonal tiles only) ----
            if (kt >= 2 * qblk) {
                int rg0 = q0 + w * 16 + (lane >> 2);
#pragma unroll
                for (int nt = 0; nt < 8; nt++) {
                    int c0 = kt * 64 + nt * 8 + (lane & 3) * 2;
                    if (c0     > rg0)     s[nt][0] = -1e30f;
                    if (c0 + 1 > rg0)     s[nt][1] = -1e30f;
                    if (c0     > rg0 + 8) s[nt][2] = -1e30f;
                    if (c0 + 1 > rg0 + 8) s[nt][3] = -1e30f;
                }
            }

            // ---- online softmax (scores are in log2 domain) ----
            float mx0 = -1e30f, mx1 = -1e30f;
#pragma unroll
            for (int nt = 0; nt < 8; nt++) {
                mx0 = fmaxf(mx0, fmaxf(s[nt][0], s[nt][1]));
                mx1 = fmaxf(mx1, fmaxf(s[nt][2], s[nt][3]));
            }
            mx0 = fmaxf(mx0, __shfl_xor_sync(0xffffffffu, mx0, 1));
            mx0 = fmaxf(mx0, __shfl_xor_sync(0xffffffffu, mx0, 2));
            mx1 = fmaxf(mx1, __shfl_xor_sync(0xffffffffu, mx1, 1));
            mx1 = fmaxf(mx1, __shfl_xor_sync(0xffffffffu, mx1, 2));
            float nm0 = fmaxf(m0, mx0), nm1 = fmaxf(m1, mx1);
            float cr0 = ex2(m0 - nm0), cr1 = ex2(m1 - nm1);
            m0 = nm0; m1 = nm1;
            float ps0 = 0.f, ps1 = 0.f;
#pragma unroll
            for (int nt = 0; nt < 8; nt++) {
                s[nt][0] = ex2(s[nt][0] - m0);
                s[nt][1] = ex2(s[nt][1] - m0);
                s[nt][2] = ex2(s[nt][2] - m1);
                s[nt][3] = ex2(s[nt][3] - m1);
                ps0 += s[nt][0] + s[nt][1];
                ps1 += s[nt][2] + s[nt][3];
            }
            ps0 += __shfl_xor_sync(0xffffffffu, ps0, 1);
            ps0 += __shfl_xor_sync(0xffffffffu, ps0, 2);
            ps1 += __shfl_xor_sync(0xffffffffu, ps1, 1);
            ps1 += __shfl_xor_sync(0xffffffffu, ps1, 2);
            l0 = l0 * cr0 + ps0;
            l1 = l1 * cr1 + ps1;
#pragma unroll
            for (int nt = 0; nt < 16; nt++) {
                o[nt][0] *= cr0; o[nt][1] *= cr0;
                o[nt][2] *= cr1; o[nt][3] *= cr1;
            }

            // ---- P (fp16) a-fragments from C layout ----
            uint32_t ph[4][4];
#pragma unroll
            for (int kf = 0; kf < 4; kf++) {
                ph[kf][0] = f22u(s[2*kf][0],   s[2*kf][1]);
                ph[kf][1] = f22u(s[2*kf][2],   s[2*kf][3]);
                ph[kf][2] = f22u(s[2*kf+1][0], s[2*kf+1][1]);
                ph[kf][3] = f22u(s[2*kf+1][2], s[2*kf+1][3]);
            }

            // ---- O += P V (2-term: Vhi + Vlo) ----
#pragma unroll
            for (int kf = 0; kf < 4; kf++) {
#pragma unroll
                for (int ntp = 0; ntp < 8; ntp++) {
                    int dn = ntp * 16 + (g >> 1) * 8 + r8;
                    int ck = kf * 2 + (g & 1);
                    uint32_t ad = stg + FV_HI + off128(dn, ck);
                    uint32_t t0, t1, t2, t3;
                    LDM_X4(t0, t1, t2, t3, ad);
                    uint32_t b0[2] = {t0, t1}, b1[2] = {t2, t3};
                    mma16816(o[2*ntp],   ph[kf], b0);
                    mma16816(o[2*ntp+1], ph[kf], b1);
                    LDM_X4(t0, t1, t2, t3, ad + 16384);
                    uint32_t c0a[2] = {t0, t1}, c1a[2] = {t2, t3};
                    mma16816(o[2*ntp],   ph[kf], c0a);
                    mma16816(o[2*ntp+1], ph[kf], c1a);
                }
            }
        }
        __syncthreads();
    }

    // epilogue
    float i0 = 1.f / l0, i1 = 1.f / l1;
    int er = lane >> 2, ec = (lane & 3) * 2;
    size_t row0 = (size_t)b * SS + q0 + w * 16 + er;
    float* d0 = attn + row0 * (NH*DD) + (size_t)h * DD;
    float* d1 = attn + (row0 + 8) * (NH*DD) + (size_t)h * DD;
#pragma unroll
    for (int nt = 0; nt < 16; nt++) {
        *(float2*)(d0 + nt * 8 + ec) = make_float2(o[nt][0] * i0, o[nt][1] * i0);
        *(float2*)(d1 + nt * 8 + ec) = make_float2(o[nt][2] * i1, o[nt][3] * i1);
    }
    #undef LOAD_KV
}

// ---------------- launch ----------------
extern "C" void kernel_launch(void* const* d_in, const int* in_sizes, int n_in,
                              void* d_out, int out_size)
{
    const float* X    = (const float*)d_in[0];
    const float* Wq   = (const float*)d_in[1];
    const float* Wk   = (const float*)d_in[2];
    const float* Wv   = (const float*)d_in[3];
    const float* Wo   = (const float*)d_in[4];
    const float* cosc = (const float*)d_in[5];
    const float* sinc = (const float*)d_in[6];
    float* out = (float*)d_out;

    float *gq, *gk, *gv, *gattn;
    __half *gXhi, *gXlo, *gAhi, *gAlo;
    __half *gWqh, *gWql, *gWkh, *gWkl, *gWvh, *gWvl, *gWoh, *gWol;
    __half *gQfh, *gQfl, *gKfh, *gKfl, *gVTh, *gVTl;
    cudaGetSymbolAddress((void**)&gq,    g_q);
    cudaGetSymbolAddress((void**)&gk,    g_k);
    cudaGetSymbolAddress((void**)&gv,    g_v);
    cudaGetSymbolAddress((void**)&gattn, g_attn);
    cudaGetSymbolAddress((void**)&gXhi,  g_Xhi);
    cudaGetSymbolAddress((void**)&gXlo,  g_Xlo);
    cudaGetSymbolAddress((void**)&gAhi,  g_Ahi);
    cudaGetSymbolAddress((void**)&gAlo,  g_Alo);
    cudaGetSymbolAddress((void**)&gWqh,  g_Wqt_hi);
    cudaGetSymbolAddress((void**)&gWql,  g_Wqt_lo);
    cudaGetSymbolAddress((void**)&gWkh,  g_Wkt_hi);
    cudaGetSymbolAddress((void**)&gWkl,  g_Wkt_lo);
    cudaGetSymbolAddress((void**)&gWvh,  g_Wvt_hi);
    cudaGetSymbolAddress((void**)&gWvl,  g_Wvt_lo);
    cudaGetSymbolAddress((void**)&gWoh,  g_Wot_hi);
    cudaGetSymbolAddress((void**)&gWol,  g_Wot_lo);
    cudaGetSymbolAddress((void**)&gQfh,  g_Qfhi);
    cudaGetSymbolAddress((void**)&gQfl,  g_Qflo);
    cudaGetSymbolAddress((void**)&gKfh,  g_Kfhi);
    cudaGetSymbolAddress((void**)&gKfl,  g_Kflo);
    cudaGetSymbolAddress((void**)&gVTh,  g_VThi);
    cudaGetSymbolAddress((void**)&gVTl,  g_VTlo);

    static bool attr_set = false;
    if (!attr_set) {
        cudaFuncSetAttribute(hgemm3_kernel, cudaFuncAttributeMaxDynamicSharedMemorySize,
                             GEMM_SMEM_TOTAL);
        cudaFuncSetAttribute(flash_mma_kernel, cudaFuncAttributeMaxDynamicSharedMemorySize,
                             FLASH_SMEM);
        attr_set = true;
    }

    // prep
    split_kernel<<<(TT*HID)/1024, 256>>>(X, gXhi, gXlo);
    transpose_split_kernel<<<dim3(HID/32, HID/32), dim3(32, 8)>>>(Wq, gWqh, gWql, HID, HID);
    transpose_split_kernel<<<dim3((NKV*DD)/32, HID/32), dim3(32, 8)>>>(Wk, gWkh, gWkl, HID, NKV*DD);
    transpose_split_kernel<<<dim3((NKV*DD)/32, HID/32), dim3(32, 8)>>>(Wv, gWvh, gWvl, HID, NKV*DD);
    transpose_split_kernel<<<dim3(HID/32, HID/32), dim3(32, 8)>>>(Wo, gWoh, gWol, HID, HID);

    // QKV projections (tensor cores)
    hgemm3_kernel<<<dim3(HID/GBN, TT/GBM), 256, GEMM_SMEM_TOTAL>>>(
        gXhi, gXlo, gWqh, gWql, gq, TT, HID, HID);
    hgemm3_kernel<<<dim3((NKV*DD)/GBN, TT/GBM), 256, GEMM_SMEM_TOTAL>>>(
        gXhi, gXlo, gWkh, gWkl, gk, TT, NKV*DD, HID);
    hgemm3_kernel<<<dim3((NKV*DD)/GBN, TT/GBM), 256, GEMM_SMEM_TOTAL>>>(
        gXhi, gXlo, gWvh, gWvl, gv, TT, NKV*DD, HID);

    // RoPE + transpose into fp16 hi/lo flash operands
    rope_q_f16<<<(TT*NH*DD)/256, 256>>>(gq, cosc, sinc, gQfh, gQfl);
    rope_k_f16<<<(TT*NKV*DD)/256, 256>>>(gk, cosc, sinc, gKfh, gKfl);
    transpose_v_f16<<<dim3(SS/32, DD/32, BB*NKV), dim3(32, 8)>>>(gv, gVTh, gVTl);

    // flash attention (tensor cores)
    flash_mma_kernel<<<dim3(SS/128, NH, BB), 256, FLASH_SMEM>>>(
        gQfh, gQfl, gKfh, gKfl, gVTh, gVTl, gattn);

    // o_proj (tensor cores)
    split_kernel<<<(TT*HID)/1024, 256>>>(gattn, gAhi, gAlo);
    hgemm3_kernel<<<dim3(HID/GBN, TT/GBM), 256, GEMM_SMEM_TOTAL>>>(
        gAhi, gAlo, gWoh, gWol, out, TT, HID, HID);
}